// round 8
// baseline (speedup 1.0000x reference)
#include <cuda_runtime.h>

// Magnus2: x_{n+1} = E_n x_n, 2x2 time-dependent, batch-independent E.
//   K1: compute E + block-local (128-slot) fp32 scan; last-finishing block
//       computes all 64 exclusive block prefixes (fp64 warp scan) -> g_pref
//   K3: (PDL-overlapped) stage P[n] = L[n] @ pref, stream y = P @ x0.

#define MAX_T   8192
#define SPB     128                 // slots per scan block
#define MAX_NB  (MAX_T / SPB)       // 64
#define NCHUNK  32                  // n-rows per out-block (1024 blocks, all resident)

__device__ float4   g_L[MAX_T];     // block-local inclusive products
__device__ float4   g_agg[MAX_NB];  // per-scan-block aggregates
__device__ float4   g_pref[MAX_NB]; // exclusive prefixes (g_pref[0] = I)
__device__ unsigned g_count;        // monotonic; (old+1) % gridDim.x == 0 -> last block

// fp32 2x2 multiply: R = X @ Y  (x=00 y=01 z=10 w=11)
__device__ __forceinline__ float4 mmul32(float4 X, float4 Y) {
    float4 r;
    r.x = X.x * Y.x + X.y * Y.z;
    r.y = X.x * Y.y + X.y * Y.w;
    r.z = X.z * Y.x + X.w * Y.z;
    r.w = X.z * Y.y + X.w * Y.w;
    return r;
}

struct M2d { double a, b, c, d; };
__device__ __forceinline__ M2d mmul64(const M2d& X, const M2d& Y) {
    M2d r;
    r.a = X.a * Y.a + X.b * Y.c;
    r.b = X.a * Y.b + X.b * Y.d;
    r.c = X.c * Y.a + X.d * Y.c;
    r.d = X.c * Y.b + X.d * Y.d;
    return r;
}
__device__ __forceinline__ M2d toD(float4 v) {
    return { (double)v.x, (double)v.y, (double)v.z, (double)v.w };
}
__device__ __forceinline__ float4 toF(const M2d& v) {
    return make_float4((float)v.a, (float)v.b, (float)v.c, (float)v.d);
}

__device__ __forceinline__ float4 shflup4(float4 v, int off) {
    float4 r;
    r.x = __shfl_up_sync(0xFFFFFFFFu, v.x, off);
    r.y = __shfl_up_sync(0xFFFFFFFFu, v.y, off);
    r.z = __shfl_up_sync(0xFFFFFFFFu, v.z, off);
    r.w = __shfl_up_sync(0xFFFFFFFFu, v.w, off);
    return r;
}
__device__ __forceinline__ M2d shflupD(const M2d& v, int off) {
    M2d r;
    r.a = __shfl_up_sync(0xFFFFFFFFu, v.a, off);
    r.b = __shfl_up_sync(0xFFFFFFFFu, v.b, off);
    r.c = __shfl_up_sync(0xFFFFFFFFu, v.c, off);
    r.d = __shfl_up_sync(0xFFFFFFFFu, v.d, off);
    return r;
}

// sin(x) for |x| up to ~1e3: Cody-Waite 2-term reduction + MUFU sin.
__device__ __forceinline__ float fast_sin(float x) {
    float k = rintf(x * 0.15915494309189535f);
    float r = fmaf(k, -6.2831855f, x);
    r = fmaf(k, 1.7484555e-7f, r);
    return __sinf(r);
}

// ---------------------------------------------------------------------------
// K1
// ---------------------------------------------------------------------------
__global__ void __launch_bounds__(SPB)
k1_E_scan(const float* __restrict__ t,
          const float* __restrict__ p_w,
          const float* __restrict__ p_g0,
          const float* __restrict__ p_ga,
          const float* __restrict__ p_wd,
          const int*   __restrict__ p_uc,
          int T)
{
    __shared__ float4 sWA[4], sWP[4];
    __shared__ int sLast;
    const int tid  = threadIdx.x;
    const int lane = tid & 31;
    const int wid  = tid >> 5;
    const int s    = blockIdx.x * SPB + tid;

    float4 E = make_float4(1.0f, 0.0f, 0.0f, 1.0f);
    if (s >= 1 && s < T) {
        const float w  = *p_w;
        const float g0 = *p_g0;
        const float ga = *p_ga;
        const float wd = *p_wd;
        const int   uc = *p_uc;

        const int i = s - 1;
        const float t0 = t[i];
        const float t1 = t[i + 1];
        const float dt = t1 - t0;
        const float tm = t0 + dt * 0.5f;
        const float gm = g0 * (1.0f + ga * fast_sin(wd * tm));

        float O00 = 0.0f;
        float O01 = dt;
        float O10 = -w * dt;
        float O11 = -gm * dt;
        if (uc) {
            const float gA = g0 * (1.0f + ga * fast_sin(wd * t0));
            const float gB = g0 * (1.0f + ga * fast_sin(wd * t1));
            const float dg = gA - gB;
            const float c  = dt * dt * (1.0f / 12.0f);
            O01 += c * dg;
            O10 += c * w * dg;
        }

        const float m     = 0.5f * (O00 + O11);
        const float det   = O00 * O11 - O01 * O10;
        const float delta = m * m - det;

        float cosl, sinch;
        if (fabsf(delta) < 0.01f) {
            cosl  = 1.0f + delta * (0.5f + delta * (1.0f / 24.0f));
            sinch = 1.0f + delta * ((1.0f / 6.0f) + delta * (1.0f / 120.0f));
        } else {
            const float sq    = sqrtf(fabsf(delta));
            const bool  pos   = (delta >= 0.0f);
            const bool  smll  = (sq < 1e-6f);
            const float ssafe = smll ? 1.0f : sq;
            cosl  = pos ? coshf(sq) : cosf(sq);
            sinch = smll ? 1.0f : ((pos ? sinhf(ssafe) : sinf(ssafe)) / ssafe);
        }
        const float em = __expf(m);

        E.x = em * (cosl + sinch * (O00 - m));
        E.y = em * (sinch * O01);
        E.z = em * (sinch * O10);
        E.w = em * (cosl + sinch * (O11 - m));
    }

    // warp-level inclusive scan (combine: newer @ older; adjacent segments)
    float4 agg = E;
    #pragma unroll
    for (int off = 1; off < 32; off <<= 1) {
        float4 prev = shflup4(agg, off);
        if (lane >= off) agg = mmul32(agg, prev);
    }
    if (lane == 31) sWA[wid] = agg;
    __syncthreads();
    if (tid == 0) {
        float4 p = make_float4(1.0f, 0.0f, 0.0f, 1.0f);
        #pragma unroll
        for (int wi = 0; wi < 4; wi++) { sWP[wi] = p; p = mmul32(sWA[wi], p); }
    }
    __syncthreads();
    if (wid > 0) agg = mmul32(agg, sWP[wid]);

    if (s < T) g_L[s] = agg;

    // publish aggregate; detect last-finishing block (monotonic, replay-safe)
    if (tid == SPB - 1) {
        g_agg[blockIdx.x] = agg;
        __threadfence();
        unsigned old = atomicAdd(&g_count, 1u);
        sLast = (((old + 1) % gridDim.x) == 0) ? 1 : 0;
    }
    __syncthreads();

    // last block: one-warp fp64 scan over NB aggregates -> exclusive prefixes
    if (sLast && wid == 0) {
        __threadfence();
        const int NB = gridDim.x;      // 64 for T=8192
        const int i0 = 2 * lane, i1 = 2 * lane + 1;
        const M2d I = {1.0, 0.0, 0.0, 1.0};
        M2d a0 = (i0 < NB) ? toD(g_agg[i0]) : I;
        M2d a1 = (i1 < NB) ? toD(g_agg[i1]) : I;
        M2d p  = mmul64(a1, a0);       // pair product, ordered newer@older
        #pragma unroll
        for (int off = 1; off < 32; off <<= 1) {
            M2d prev = shflupD(p, off);
            if (lane >= off) p = mmul64(p, prev);
        }
        M2d Sm1 = shflupD(p, 1);
        M2d pref0 = (lane == 0) ? I : Sm1;
        M2d pref1 = mmul64(a0, pref0);
        if (i0 < MAX_NB) g_pref[i0] = toF(pref0);
        if (i1 < MAX_NB) g_pref[i1] = toF(pref1);
    }
}

// ---------------------------------------------------------------------------
// K3: PDL secondary. gridDependencySynchronize, stage P, stream stores.
// __launch_bounds__(256, 8) -> <=32 regs -> 8 CTAs/SM -> all 1024 resident.
// ---------------------------------------------------------------------------
__global__ void __launch_bounds__(256, 8)
k3_out(const float* __restrict__ x0,
       float* __restrict__ out,
       int B, int T)
{
    __shared__ float4 sP[NCHUNK];
    const int tid = threadIdx.x;
    const int B4  = B >> 2;
    const int b4  = blockIdx.x * 256 + tid;
    const int n0  = blockIdx.y * NCHUNK;

    cudaGridDependencySynchronize();   // k1's writes fully visible after this

    if (tid < NCHUNK) {
        int nn = n0 + tid;
        if (nn >= T) nn = T - 1;
        float4 L  = g_L[nn];
        float4 pr = g_pref[n0 >> 7];   // SPB == 128; constant over the chunk
        sP[tid] = mmul32(L, pr);       // g_pref[0] == I
    }
    __syncthreads();

    if (b4 >= B4) return;

    const float4 a0 = ((const float4*)x0)[b4];
    const float4 a1 = ((const float4*)(x0 + B))[b4];

    float4* o = (float4*)out + (size_t)n0 * 2 * B4 + b4;

    #pragma unroll 4
    for (int j = 0; j < NCHUNK; j++) {
        const int n = n0 + j;
        if (n >= T) break;
        const float4 P = sP[j];

        float4 y0, y1;
        y0.x = P.x * a0.x + P.y * a1.x;
        y0.y = P.x * a0.y + P.y * a1.y;
        y0.z = P.x * a0.z + P.y * a1.z;
        y0.w = P.x * a0.w + P.y * a1.w;
        y1.x = P.z * a0.x + P.w * a1.x;
        y1.y = P.z * a0.y + P.w * a1.y;
        y1.z = P.z * a0.z + P.w * a1.z;
        y1.w = P.z * a0.w + P.w * a1.w;

        __stcs(o, y0);
        __stcs(o + B4, y1);
        o += 2 * B4;
    }
}

// ---------------------------------------------------------------------------
extern "C" void kernel_launch(void* const* d_in, const int* in_sizes, int n_in,
                              void* d_out, int out_size)
{
    const float* t  = (const float*)d_in[0];
    const float* x0 = (const float*)d_in[1];
    const float* w  = (const float*)d_in[2];
    const float* g0 = (const float*)d_in[3];
    const float* ga = (const float*)d_in[4];
    const float* wd = (const float*)d_in[5];
    const int*   uc = (const int*)d_in[6];
    float* out = (float*)d_out;

    const int T = in_sizes[0];       // 8192
    const int B = in_sizes[1] / 2;   // 4096
    const int NB = (T + SPB - 1) / SPB;   // 64

    k1_E_scan<<<NB, SPB>>>(t, w, g0, ga, wd, uc, T);

    {
        const int B4 = B >> 2;
        cudaLaunchConfig_t cfg = {};
        cfg.gridDim  = dim3((B4 + 255) / 256, (T + NCHUNK - 1) / NCHUNK, 1);
        cfg.blockDim = dim3(256, 1, 1);
        cfg.dynamicSmemBytes = 0;
        cfg.stream = 0;
        cudaLaunchAttribute attrs[1];
        attrs[0].id = cudaLaunchAttributeProgrammaticStreamSerialization;
        attrs[0].val.programmaticStreamSerializationAllowed = 1;
        cfg.attrs = attrs;
        cfg.numAttrs = 1;
        cudaLaunchKernelEx(&cfg, k3_out, x0, out, B, T);
    }
}